// round 14
// baseline (speedup 1.0000x reference)
#include <cuda_runtime.h>

#define BSZ  2
#define DM   256
#define LSEQ 4096
#define DI   256
#define DS   16
#define NC   32
#define CHUNK (LSEQ / NC)   // 128
#define ROWP 132            // padded smem row stride (floats)

// ---------------- scratch (static device globals; no runtime alloc) ----------
__device__ float g_xs [BSZ*LSEQ*DI];   // in-proj left half          [b][l][d]
__device__ float g_szT[BSZ*DI*LSEQ];   // silu(z) TRANSPOSED         [b][d][l]
__device__ float g_xc [BSZ*DI*LSEQ];   // conv+silu output           [b][d][l]
__device__ float g_dt [BSZ*DI*LSEQ];   // softplus(dt)               [b][d][l]
__device__ float g_Bm [BSZ*LSEQ*DS];   // B packed  [b][l/4][s][l%4]
__device__ float g_Cm [BSZ*LSEQ*DS];   // C packed  [b][l/4][s][l%4]
__device__ float g_ymT[BSZ*DI*LSEQ];   // (y + xc*D)*silu(z)         [b][d][l]
__device__ float g_S  [BSZ*DI*NC*DS];  // chunk-final local states
__device__ float g_P  [BSZ*DI*NC*DS];  // chunk decay products

typedef unsigned long long u64;

__device__ __forceinline__ u64 pack2(float lo, float hi) {
    u64 r; asm("mov.b64 %0, {%1, %2};" : "=l"(r) : "f"(lo), "f"(hi)); return r;
}
__device__ __forceinline__ void unpack2(u64 v, float& lo, float& hi) {
    asm("mov.b64 {%0, %1}, %2;" : "=f"(lo), "=f"(hi) : "l"(v));
}
__device__ __forceinline__ u64 fma2(u64 a, u64 b, u64 c) {
    u64 d; asm("fma.rn.f32x2 %0, %1, %2, %3;" : "=l"(d) : "l"(a), "l"(b), "l"(c)); return d;
}
__device__ __forceinline__ float silu_f(float v) { return v / (1.f + __expf(-v)); }
__device__ __forceinline__ float ex2f(float v) {
    float r; asm("ex2.approx.ftz.f32 %0, %1;" : "=f"(r) : "f"(v)); return r;
}
#define LOG2E 1.4426950408889634f

__device__ __forceinline__ void cp_async16(void* smem, const void* g) {
    unsigned sa = (unsigned)__cvta_generic_to_shared(smem);
    asm volatile("cp.async.cg.shared.global [%0], [%1], 16;\n" :: "r"(sa), "l"(g));
}
__device__ __forceinline__ void cp_commit() {
    asm volatile("cp.async.commit_group;\n");
}
__device__ __forceinline__ void cp_wait0() {
    asm volatile("cp.async.wait_group 0;\n");
}

// Exchange-halving butterfly: reduce 16 independent sums across 16 lanes.
__device__ __forceinline__ float hreduce16(float* w, int s) {
#pragma unroll
    for (int i = 0; i < 8; i++) {
        float snd = (s & 8) ? w[i] : w[i + 8];
        float kp  = (s & 8) ? w[i + 8] : w[i];
        w[i] = kp + __shfl_xor_sync(0xffffffffu, snd, 8, 16);
    }
#pragma unroll
    for (int i = 0; i < 4; i++) {
        float snd = (s & 4) ? w[i] : w[i + 4];
        float kp  = (s & 4) ? w[i + 4] : w[i];
        w[i] = kp + __shfl_xor_sync(0xffffffffu, snd, 4, 16);
    }
#pragma unroll
    for (int i = 0; i < 2; i++) {
        float snd = (s & 2) ? w[i] : w[i + 2];
        float kp  = (s & 2) ? w[i + 2] : w[i];
        w[i] = kp + __shfl_xor_sync(0xffffffffu, snd, 2, 16);
    }
    {
        float snd = (s & 1) ? w[0] : w[1];
        float kp  = (s & 1) ? w[1] : w[0];
        w[0] = kp + __shfl_xor_sync(0xffffffffu, snd, 1, 16);
    }
    return w[0];
}

// ============================================================================
// K1: in-projection GEMM.  out[b,l,j] = sum_c x[b,c,l] * W_in[c,j]
// 64(l) x 128(j) tiles, K-tiles of 16.
// A tile stored DUPLICATED in smem ([v,v] pairs) -> aa comes packed from LDS.
// B via cp.async double-buffer; thread = 4 rows x 8 contiguous cols.
// ============================================================================
__global__ __launch_bounds__(256) void k_inproj(const float* __restrict__ x,
                                                const float* __restrict__ Win) {
    __shared__ __align__(16) float Ad[2][16][136];   // 128 used (64 vals dup'd)
    __shared__ __align__(16) float Bs[2][16][ROWP];
    const int t  = threadIdx.x;
    const int l0 = blockIdx.x * 64, j0 = blockIdx.y * 128, b = blockIdx.z;
    const int ty = t >> 4, tx = t & 15;
    const float* xb = x + b * DM * LSEQ;

    u64 acc[4][4];
#pragma unroll
    for (int i = 0; i < 4; i++)
#pragma unroll
        for (int p = 0; p < 4; p++) acc[i][p] = 0ull;

    const int ka = t >> 4, ja = (t & 15) * 4;
    auto ldgA = [&](int tile) {
        return *(const float4*)(xb + (tile * 16 + ka) * LSEQ + l0 + ja);
    };
    auto stsA = [&](const float4& v, int buf) {
        float* p = &Ad[buf][ka][ja * 2];
        float4 w0; w0.x = v.x; w0.y = v.x; w0.z = v.y; w0.w = v.y;
        float4 w1; w1.x = v.z; w1.y = v.z; w1.z = v.w; w1.w = v.w;
        *(float4*)p = w0; *(float4*)(p + 4) = w1;
    };
    auto prefB = [&](int tile, int buf) {
#pragma unroll
        for (int i = 0; i < 2; i++) {
            int idx = t + i * 256;
            int kb = idx >> 5, jb = (idx & 31) * 4;
            cp_async16(&Bs[buf][kb][jb], Win + (tile * 16 + kb) * (2 * DI) + j0 + jb);
        }
    };

    float4 areg = ldgA(0);
    prefB(0, 0); cp_commit();
    stsA(areg, 0);
    float4 anext;

    for (int it = 0; it < 16; it++) {
        const int buf = it & 1;
        cp_wait0();
        __syncthreads();
        if (it + 1 < 16) { anext = ldgA(it + 1); prefB(it + 1, buf ^ 1); cp_commit(); }
#pragma unroll
        for (int k = 0; k < 16; k++) {
            ulonglong2 a01 = *(const ulonglong2*)&Ad[buf][k][ty * 8];
            ulonglong2 a23 = *(const ulonglong2*)&Ad[buf][k][ty * 8 + 4];
            ulonglong2 b01 = *(const ulonglong2*)&Bs[buf][k][tx * 8];
            ulonglong2 b23 = *(const ulonglong2*)&Bs[buf][k][tx * 8 + 4];
            acc[0][0] = fma2(a01.x, b01.x, acc[0][0]);
            acc[0][1] = fma2(a01.x, b01.y, acc[0][1]);
            acc[0][2] = fma2(a01.x, b23.x, acc[0][2]);
            acc[0][3] = fma2(a01.x, b23.y, acc[0][3]);
            acc[1][0] = fma2(a01.y, b01.x, acc[1][0]);
            acc[1][1] = fma2(a01.y, b01.y, acc[1][1]);
            acc[1][2] = fma2(a01.y, b23.x, acc[1][2]);
            acc[1][3] = fma2(a01.y, b23.y, acc[1][3]);
            acc[2][0] = fma2(a23.x, b01.x, acc[2][0]);
            acc[2][1] = fma2(a23.x, b01.y, acc[2][1]);
            acc[2][2] = fma2(a23.x, b23.x, acc[2][2]);
            acc[2][3] = fma2(a23.x, b23.y, acc[2][3]);
            acc[3][0] = fma2(a23.y, b01.x, acc[3][0]);
            acc[3][1] = fma2(a23.y, b01.y, acc[3][1]);
            acc[3][2] = fma2(a23.y, b23.x, acc[3][2]);
            acc[3][3] = fma2(a23.y, b23.y, acc[3][3]);
        }
        __syncthreads();
        if (it + 1 < 16) stsA(anext, buf ^ 1);
    }

    if (j0 < DI) {
        // xs half: 8 contiguous cols per thread -> 2 STG.128 per row
#pragma unroll
        for (int i = 0; i < 4; i++) {
            int l = l0 + ty * 4 + i;
            float v[8];
#pragma unroll
            for (int p = 0; p < 4; p++) unpack2(acc[i][p], v[2 * p], v[2 * p + 1]);
            float* dst = &g_xs[(b * LSEQ + l) * DI + j0 + tx * 8];
            float4 v0; v0.x = v[0]; v0.y = v[1]; v0.z = v[2]; v0.w = v[3];
            float4 v1; v1.x = v[4]; v1.y = v[5]; v1.z = v[6]; v1.w = v[7];
            *(float4*)dst = v0; *(float4*)(dst + 4) = v1;
        }
    } else {
        // z half: silu + transposed store [d][l]
#pragma unroll
        for (int p = 0; p < 4; p++) {
            int jlo = (j0 - DI) + tx * 8 + 2 * p;
            float lo[4], hi[4];
#pragma unroll
            for (int i = 0; i < 4; i++) unpack2(acc[i][p], lo[i], hi[i]);
            float4 v0;
            v0.x = silu_f(lo[0]); v0.y = silu_f(lo[1]); v0.z = silu_f(lo[2]); v0.w = silu_f(lo[3]);
            *(float4*)&g_szT[(b * DI + jlo) * LSEQ + l0 + ty * 4] = v0;
            float4 v1;
            v1.x = silu_f(hi[0]); v1.y = silu_f(hi[1]); v1.z = silu_f(hi[2]); v1.w = silu_f(hi[3]);
            *(float4*)&g_szT[(b * DI + jlo + 1) * LSEQ + l0 + ty * 4] = v1;
        }
    }
}

// ============================================================================
// K2: causal depthwise conv(4) + silu -> xc [d][l]; dbc = xc @ W_x;
//     dt = softplus(dbc[:, :16] @ W_dt + b_dt) -> [d][l];
//     B/C packed [l/4][s][l%4].
// ============================================================================
__global__ __launch_bounds__(256) void k_conv_proj(const float* __restrict__ convw,
                                                   const float* __restrict__ convb,
                                                   const float* __restrict__ Wx,
                                                   const float* __restrict__ Wdt,
                                                   const float* __restrict__ bdt) {
    __shared__ float xc_s[32][257];   // reused as dt staging in phase C
    __shared__ float dbc_s[32][49];
    const int t  = threadIdx.x;
    const int b  = blockIdx.x >> 7;
    const int l0 = (blockIdx.x & 127) * 32;

    // ---- Phase A: conv + silu (thread t owns channel d = t) ----
    {
        const int d = t;
        const float w0 = convw[d * 4 + 0], w1 = convw[d * 4 + 1];
        const float w2 = convw[d * 4 + 2], w3 = convw[d * 4 + 3];
        const float cb = convb[d];
        const float* pxs = g_xs + b * LSEQ * DI + d;
        float x0, x1, x2;
        if (l0 == 0) { x0 = x1 = x2 = 0.f; }
        else { x0 = pxs[(l0 - 3) * DI]; x1 = pxs[(l0 - 2) * DI]; x2 = pxs[(l0 - 1) * DI]; }
        for (int j = 0; j < 32; j++) {
            float x3 = pxs[(l0 + j) * DI];
            float c  = cb + w0 * x0 + w1 * x1 + w2 * x2 + w3 * x3;
            xc_s[j][d] = silu_f(c);
            x0 = x1; x1 = x2; x2 = x3;
        }
    }
    __syncthreads();

    // ---- transposed coalesced write of xc to [d][l] ----
    for (int i = t; i < 32 * DI; i += 256) {
        int d2 = i >> 5, r2 = i & 31;
        g_xc[(b * DI + d2) * LSEQ + l0 + r2] = xc_s[r2][d2];
    }

    // ---- Phase B: dbc[r][0..47] = xc[r] @ W_x ----
    {
        const int r = t & 31, g = t >> 5;   // g in 0..7, 6 cols each
        float acc[6];
#pragma unroll
        for (int jj = 0; jj < 6; jj++) acc[jj] = 0.f;
        const float* wbase = Wx + g * 6;
        for (int c = 0; c < DI; c++) {
            float xv = xc_s[r][c];
            const float2* wp = (const float2*)(wbase + c * 48);
            float2 wa = __ldg(wp), wb = __ldg(wp + 1), wc = __ldg(wp + 2);
            acc[0] = fmaf(xv, wa.x, acc[0]); acc[1] = fmaf(xv, wa.y, acc[1]);
            acc[2] = fmaf(xv, wb.x, acc[2]); acc[3] = fmaf(xv, wb.y, acc[3]);
            acc[4] = fmaf(xv, wc.x, acc[4]); acc[5] = fmaf(xv, wc.y, acc[5]);
        }
#pragma unroll
        for (int jj = 0; jj < 6; jj++) dbc_s[r][g * 6 + jj] = acc[jj];
    }
    __syncthreads();

    // ---- Phase C: dt = softplus(dbc[:, :16] @ W_dt + b_dt) into xc_s ----
    {
        const int d = t;
        float wdt[16];
#pragma unroll
        for (int k = 0; k < 16; k++) wdt[k] = Wdt[k * DI + d];
        const float bd = bdt[d];
        for (int r = 0; r < 32; r++) {
            float a = bd;
#pragma unroll
            for (int k = 0; k < 16; k++) a = fmaf(dbc_s[r][k], wdt[k], a);
            xc_s[r][d] = (a > 20.f) ? a : log1pf(__expf(a));
        }
    }
    __syncthreads();

    // ---- transposed coalesced write of dt to [d][l] ----
    for (int i = t; i < 32 * DI; i += 256) {
        int d2 = i >> 5, r2 = i & 31;
        g_dt[(b * DI + d2) * LSEQ + l0 + r2] = xc_s[r2][d2];
    }

    // ---- packed coalesced write of B / C: [l/4][s][l%4] ----
    {
        const int base = (b * LSEQ + l0) * DS;
        for (int i = t; i < 32 * DS; i += 256) {
            int g4 = i >> 6, s = (i >> 2) & 15, r2 = i & 3;
            int r = g4 * 4 + r2;
            g_Bm[base + i] = dbc_s[r][16 + s];
            g_Cm[base + i] = dbc_s[r][32 + s];
        }
    }
}

// ============================================================================
// K3a: per-chunk local scan -> S (final h with h0=0) and P = exp2(A2 * sum dt).
// Block = 16 d's x one chunk; working set staged in smem via one cp.async burst.
// ============================================================================
__global__ __launch_bounds__(256) void k_scan1(const float* __restrict__ Alog) {
    __shared__ __align__(16) float s_dt[16 * ROWP];
    __shared__ __align__(16) float s_xc[16 * ROWP];
    __shared__ __align__(16) float s_B [CHUNK * DS];

    const int t  = threadIdx.x;
    const int dg    = blockIdx.x & 15;
    const int chunk = (blockIdx.x >> 4) & (NC - 1);
    const int b     = blockIdx.x >> 9;
    const int d0 = dg * 16;
    const int l0 = chunk * CHUNK;

    const float* pdt_g = g_dt + (b * DI + d0) * LSEQ + l0;
    const float* pxc_g = g_xc + (b * DI + d0) * LSEQ + l0;
    const float* pB_g  = g_Bm + (b * LSEQ + l0) * DS;

#pragma unroll
    for (int i = t; i < 512 * 3; i += 256) {
        int r = i >> 9, j = i & 511;
        int w = j >> 5, j16 = (j & 31) * 4;
        if (r == 0)      cp_async16(&s_dt[w * ROWP + j16], pdt_g + w * LSEQ + j16);
        else if (r == 1) cp_async16(&s_xc[w * ROWP + j16], pxc_g + w * LSEQ + j16);
        else             cp_async16(&s_B[j * 4], pB_g + j * 4);
    }
    cp_commit(); cp_wait0();
    __syncthreads();

    const int w = t >> 4, s = t & 15;
    const int d = d0 + w;
    const float A2 = -__expf(Alog[d * DS + s]) * LOG2E;
    const float* sdt = s_dt + w * ROWP;
    const float* sxc = s_xc + w * ROWP;
    const float* sB  = s_B + s * 4;

    float h = 0.f, dts = 0.f;
#pragma unroll 8
    for (int l = 0; l < CHUNK; l += 4) {
        float4 dv = *(const float4*)(sdt + l);
        float4 xv = *(const float4*)(sxc + l);
        float4 Bv = *(const float4*)(sB + (l >> 2) * 64);
        h = fmaf(h, ex2f(dv.x * A2), dv.x * xv.x * Bv.x);
        h = fmaf(h, ex2f(dv.y * A2), dv.y * xv.y * Bv.y);
        h = fmaf(h, ex2f(dv.z * A2), dv.z * xv.z * Bv.z);
        h = fmaf(h, ex2f(dv.w * A2), dv.w * xv.w * Bv.w);
        dts += (dv.x + dv.y) + (dv.z + dv.w);
    }
    const int idx = ((b * DI + d) * NC + chunk) * DS + s;
    g_S[idx] = h;
    g_P[idx] = ex2f(A2 * dts);
}

// ============================================================================
// K3b: per-chunk scan with true initial state (self-stitched prefix).
// Block = 16 d's x one chunk; 40 KB smem staging. Butterfly reduction.
// Emits g_ymT = (y + xc*D) * silu(z)   in [b][d][l] layout (coalesced store).
// ============================================================================
__global__ __launch_bounds__(256) void k_scan3(const float* __restrict__ Alog,
                                               const float* __restrict__ Dvec) {
    __shared__ __align__(16) float s_dt[16 * ROWP];
    __shared__ __align__(16) float s_xc[16 * ROWP];
    __shared__ __align__(16) float s_sz[16 * ROWP];
    __shared__ __align__(16) float s_B [CHUNK * DS];
    __shared__ __align__(16) float s_C [CHUNK * DS];

    const int t  = threadIdx.x;
    const int dg    = blockIdx.x & 15;
    const int chunk = (blockIdx.x >> 4) & (NC - 1);
    const int b     = blockIdx.x >> 9;
    const int d0 = dg * 16;
    const int l0 = chunk * CHUNK;

    const float* pdt_g = g_dt  + (b * DI + d0) * LSEQ + l0;
    const float* pxc_g = g_xc  + (b * DI + d0) * LSEQ + l0;
    const float* psz_g = g_szT + (b * DI + d0) * LSEQ + l0;
    const float* pB_g  = g_Bm  + (b * LSEQ + l0) * DS;
    const float* pC_g  = g_Cm  + (b * LSEQ + l0) * DS;

#pragma unroll
    for (int i = t; i < 512 * 5; i += 256) {
        int r = i >> 9, j = i & 511;
        int w = j >> 5, j16 = (j & 31) * 4;
        if (r == 0)      cp_async16(&s_dt[w * ROWP + j16], pdt_g + w * LSEQ + j16);
        else if (r == 1) cp_async16(&s_xc[w * ROWP + j16], pxc_g + w * LSEQ + j16);
        else if (r == 2) cp_async16(&s_sz[w * ROWP + j16], psz_g + w * LSEQ + j16);
        else if (r == 3) cp_async16(&s_B[j * 4], pB_g + j * 4);
        else             cp_async16(&s_C[j * 4], pC_g + j * 4);
    }
    cp_commit();

    const int w = t >> 4, s = t & 15;
    const int d = d0 + w;
    const float A2 = -__expf(Alog[d * DS + s]) * LOG2E;
    const float Dd = Dvec[d];
    float*       pyT = g_ymT + (b * DI + d) * LSEQ + l0;

    // ---- self-stitched prefix (overlaps with the cp.async fill) ----
    float h = 0.f;
    {
        const int pbase = (b * DI + d) * NC * DS + s;
#pragma unroll
        for (int c = 0; c < NC - 1; c++) {
            if (c < chunk) h = fmaf(g_P[pbase + c * DS], h, g_S[pbase + c * DS]);
        }
    }

    cp_wait0();
    __syncthreads();

    const float* sdt = s_dt + w * ROWP;
    const float* sxc = s_xc + w * ROWP;
    const float* ssz = s_sz + w * ROWP;
    const float* sB  = s_B + s * 4;
    const float* sC  = s_C + s * 4;

    for (int l = 0; l < CHUNK; l += 16) {
        float wv[16];
#pragma unroll
        for (int g = 0; g < 4; g++) {
            float4 dv = *(const float4*)(sdt + l + g * 4);
            float4 xv = *(const float4*)(sxc + l + g * 4);
            float4 Bv = *(const float4*)(sB + ((l >> 2) + g) * 64);
            float4 Cv = *(const float4*)(sC + ((l >> 2) + g) * 64);
            h = fmaf(h, ex2f(dv.x * A2), dv.x * xv.x * Bv.x); wv[g * 4 + 0] = h * Cv.x;
            h = fmaf(h, ex2f(dv.y * A2), dv.y * xv.y * Bv.y); wv[g * 4 + 1] = h * Cv.y;
            h = fmaf(h, ex2f(dv.z * A2), dv.z * xv.z * Bv.z); wv[g * 4 + 2] = h * Cv.z;
            h = fmaf(h, ex2f(dv.w * A2), dv.w * xv.w * Bv.w); wv[g * 4 + 3] = h * Cv.w;
        }
        float y  = hreduce16(wv, s);
        float xs = sxc[l + s];
        float zs = ssz[l + s];
        pyT[l + s] = fmaf(xs, Dd, y) * zs;
    }
}

// ============================================================================
// K4: out-projection GEMM.  out[b,c,l] = sum_d ymT[b,d,l] * W_out[d,c]
// 64(c) x 128(l) tiles; A (Wout) duplicated in smem, B (ymT) cp.async.
// ============================================================================
__global__ __launch_bounds__(256) void k_outproj(const float* __restrict__ Wout,
                                                 float* __restrict__ out) {
    __shared__ __align__(16) float Ad[2][16][136];
    __shared__ __align__(16) float Bs[2][16][ROWP];
    const int t  = threadIdx.x;
    const int l0 = blockIdx.x * 128, c0 = blockIdx.y * 64, b = blockIdx.z;
    const int ty = t >> 4, tx = t & 15;

    u64 acc[4][4];
#pragma unroll
    for (int i = 0; i < 4; i++)
#pragma unroll
        for (int p = 0; p < 4; p++) acc[i][p] = 0ull;

    const float* ymb = g_ymT + b * DI * LSEQ;
    const int ka = t >> 4, ja = (t & 15) * 4;
    auto ldgA = [&](int tile) {
        return *(const float4*)(Wout + (tile * 16 + ka) * DM + c0 + ja);
    };
    auto stsA = [&](const float4& v, int buf) {
        float* p = &Ad[buf][ka][ja * 2];
        float4 w0; w0.x = v.x; w0.y = v.x; w0.z = v.y; w0.w = v.y;
        float4 w1; w1.x = v.z; w1.y = v.z; w1.z = v.w; w1.w = v.w;
        *(float4*)p = w0; *(float4*)(p + 4) = w1;
    };
    auto prefB = [&](int tile, int buf) {
#pragma unroll
        for (int i = 0; i < 2; i++) {
            int idx = t + i * 256;
            int kb = idx >> 5, lb = (idx & 31) * 4;
            cp_async16(&Bs[buf][kb][lb], ymb + (tile * 16 + kb) * LSEQ + l0 + lb);
        }
    };

    float4 areg = ldgA(0);
    prefB(0, 0); cp_commit();
    stsA(areg, 0);
    float4 anext;

    for (int it = 0; it < 16; it++) {
        const int buf = it & 1;
        cp_wait0();
        __syncthreads();
        if (it + 1 < 16) { anext = ldgA(it + 1); prefB(it + 1, buf ^ 1); cp_commit(); }
#pragma unroll
        for (int k = 0; k < 16; k++) {
            ulonglong2 a01 = *(const ulonglong2*)&Ad[buf][k][ty * 8];
            ulonglong2 a23 = *(const ulonglong2*)&Ad[buf][k][ty * 8 + 4];
            ulonglong2 b01 = *(const ulonglong2*)&Bs[buf][k][tx * 8];
            ulonglong2 b23 = *(const ulonglong2*)&Bs[buf][k][tx * 8 + 4];
            acc[0][0] = fma2(a01.x, b01.x, acc[0][0]);
            acc[0][1] = fma2(a01.x, b01.y, acc[0][1]);
            acc[0][2] = fma2(a01.x, b23.x, acc[0][2]);
            acc[0][3] = fma2(a01.x, b23.y, acc[0][3]);
            acc[1][0] = fma2(a01.y, b01.x, acc[1][0]);
            acc[1][1] = fma2(a01.y, b01.y, acc[1][1]);
            acc[1][2] = fma2(a01.y, b23.x, acc[1][2]);
            acc[1][3] = fma2(a01.y, b23.y, acc[1][3]);
            acc[2][0] = fma2(a23.x, b01.x, acc[2][0]);
            acc[2][1] = fma2(a23.x, b01.y, acc[2][1]);
            acc[2][2] = fma2(a23.x, b23.x, acc[2][2]);
            acc[2][3] = fma2(a23.x, b23.y, acc[2][3]);
            acc[3][0] = fma2(a23.y, b01.x, acc[3][0]);
            acc[3][1] = fma2(a23.y, b01.y, acc[3][1]);
            acc[3][2] = fma2(a23.y, b23.x, acc[3][2]);
            acc[3][3] = fma2(a23.y, b23.y, acc[3][3]);
        }
        __syncthreads();
        if (it + 1 < 16) stsA(anext, buf ^ 1);
    }

#pragma unroll
    for (int i = 0; i < 4; i++) {
        int c = c0 + ty * 4 + i;
        float v[8];
#pragma unroll
        for (int p = 0; p < 4; p++) unpack2(acc[i][p], v[2 * p], v[2 * p + 1]);
        float* dst = &out[(b * DM + c) * LSEQ + l0 + tx * 8];
        float4 v0; v0.x = v[0]; v0.y = v[1]; v0.z = v[2]; v0.w = v[3];
        float4 v1; v1.x = v[4]; v1.y = v[5]; v1.z = v[6]; v1.w = v[7];
        *(float4*)dst = v0; *(float4*)(dst + 4) = v1;
    }
}

// ============================================================================
extern "C" void kernel_launch(void* const* d_in, const int* in_sizes, int n_in,
                              void* d_out, int out_size) {
    (void)in_sizes; (void)n_in; (void)out_size;
    const float* x     = (const float*)d_in[0];
    const float* Win   = (const float*)d_in[1];
    const float* convw = (const float*)d_in[2];
    const float* convb = (const float*)d_in[3];
    const float* Wx    = (const float*)d_in[4];
    const float* Wdt   = (const float*)d_in[5];
    const float* bdt   = (const float*)d_in[6];
    const float* Alog  = (const float*)d_in[7];
    const float* Dvec  = (const float*)d_in[8];
    const float* Wout  = (const float*)d_in[9];
    float* out = (float*)d_out;

    k_inproj   <<<dim3(64, 4, 2), 256>>>(x, Win);
    k_conv_proj<<<256, 256>>>(convw, convb, Wx, Wdt, bdt);
    k_scan1    <<<1024, 256>>>(Alog);
    k_scan3    <<<1024, 256>>>(Alog, Dvec);
    k_outproj  <<<dim3(32, 4, 2), 256>>>(Wout, out);
}

// round 15
// speedup vs baseline: 1.4068x; 1.4068x over previous
#include <cuda_runtime.h>

#define BSZ  2
#define DM   256
#define LSEQ 4096
#define DI   256
#define DS   16
#define NC   32
#define CHUNK (LSEQ / NC)   // 128
#define ROWP 132            // padded smem row stride (floats)

// ---------------- scratch (static device globals; no runtime alloc) ----------
__device__ float g_xs [BSZ*LSEQ*DI];   // in-proj left half          [b][l][d]
__device__ float g_szT[BSZ*DI*LSEQ];   // silu(z) TRANSPOSED         [b][d][l]
__device__ float g_xc [BSZ*DI*LSEQ];   // conv+silu output           [b][d][l]
__device__ float g_dt [BSZ*DI*LSEQ];   // softplus(dt)               [b][d][l]
__device__ float g_Bm [BSZ*LSEQ*DS];   // B packed  [b][l/4][s][l%4]
__device__ float g_Cm [BSZ*LSEQ*DS];   // C packed  [b][l/4][s][l%4]
__device__ float g_ymT[BSZ*DI*LSEQ];   // (y + xc*D)*silu(z)         [b][d][l]
__device__ float g_S  [BSZ*DI*NC*DS];  // chunk-final local states
__device__ float g_P  [BSZ*DI*NC*DS];  // chunk decay products

typedef unsigned long long u64;

__device__ __forceinline__ u64 pack2(float lo, float hi) {
    u64 r; asm("mov.b64 %0, {%1, %2};" : "=l"(r) : "f"(lo), "f"(hi)); return r;
}
__device__ __forceinline__ void unpack2(u64 v, float& lo, float& hi) {
    asm("mov.b64 {%0, %1}, %2;" : "=f"(lo), "=f"(hi) : "l"(v));
}
__device__ __forceinline__ u64 fma2(u64 a, u64 b, u64 c) {
    u64 d; asm("fma.rn.f32x2 %0, %1, %2, %3;" : "=l"(d) : "l"(a), "l"(b), "l"(c)); return d;
}
__device__ __forceinline__ float silu_f(float v) { return v / (1.f + __expf(-v)); }
__device__ __forceinline__ float ex2f(float v) {
    float r; asm("ex2.approx.ftz.f32 %0, %1;" : "=f"(r) : "f"(v)); return r;
}
#define LOG2E 1.4426950408889634f

__device__ __forceinline__ void cp_async16(void* smem, const void* g) {
    unsigned sa = (unsigned)__cvta_generic_to_shared(smem);
    asm volatile("cp.async.cg.shared.global [%0], [%1], 16;\n" :: "r"(sa), "l"(g));
}
__device__ __forceinline__ void cp_commit() {
    asm volatile("cp.async.commit_group;\n");
}
__device__ __forceinline__ void cp_wait0() {
    asm volatile("cp.async.wait_group 0;\n");
}

// Exchange-halving butterfly: reduce 16 independent sums across 16 lanes.
__device__ __forceinline__ float hreduce16(float* w, int s) {
#pragma unroll
    for (int i = 0; i < 8; i++) {
        float snd = (s & 8) ? w[i] : w[i + 8];
        float kp  = (s & 8) ? w[i + 8] : w[i];
        w[i] = kp + __shfl_xor_sync(0xffffffffu, snd, 8, 16);
    }
#pragma unroll
    for (int i = 0; i < 4; i++) {
        float snd = (s & 4) ? w[i] : w[i + 4];
        float kp  = (s & 4) ? w[i + 4] : w[i];
        w[i] = kp + __shfl_xor_sync(0xffffffffu, snd, 4, 16);
    }
#pragma unroll
    for (int i = 0; i < 2; i++) {
        float snd = (s & 2) ? w[i] : w[i + 2];
        float kp  = (s & 2) ? w[i + 2] : w[i];
        w[i] = kp + __shfl_xor_sync(0xffffffffu, snd, 2, 16);
    }
    {
        float snd = (s & 1) ? w[0] : w[1];
        float kp  = (s & 1) ? w[1] : w[0];
        w[0] = kp + __shfl_xor_sync(0xffffffffu, snd, 1, 16);
    }
    return w[0];
}

// ============================================================================
// K1: in-projection GEMM.  out[b,l,j] = sum_c x[b,c,l] * W_in[c,j]
// 64(l) x 128(j) tiles, K-tiles of 16, cp.async double-buffered. (R11 proven)
// ============================================================================
__global__ __launch_bounds__(256) void k_inproj(const float* __restrict__ x,
                                                const float* __restrict__ Win) {
    __shared__ float As[2][16][64];
    __shared__ float Bs[2][16][132];
    const int t  = threadIdx.x;
    const int l0 = blockIdx.x * 64, j0 = blockIdx.y * 128, b = blockIdx.z;
    const int ty = t >> 4, tx = t & 15;
    const float* xb = x + b * DM * LSEQ;

    u64 acc[4][4];
#pragma unroll
    for (int i = 0; i < 4; i++)
#pragma unroll
        for (int p = 0; p < 4; p++) acc[i][p] = 0ull;

    const int ka = t >> 4, ja = (t & 15) * 4;
    auto pref = [&](int tile, int buf) {
        cp_async16(&As[buf][ka][ja], xb + (tile * 16 + ka) * LSEQ + l0 + ja);
#pragma unroll
        for (int i = 0; i < 2; i++) {
            int idx = t + i * 256;
            int kb = idx >> 5, jb = (idx & 31) * 4;
            cp_async16(&Bs[buf][kb][jb], Win + (tile * 16 + kb) * (2 * DI) + j0 + jb);
        }
    };

    pref(0, 0); cp_commit();

    for (int it = 0; it < 16; it++) {
        const int buf = it & 1;
        cp_wait0();
        __syncthreads();
        if (it + 1 < 16) { pref(it + 1, buf ^ 1); cp_commit(); }
#pragma unroll
        for (int k = 0; k < 16; k++) {
            float4 av = *(const float4*)&As[buf][k][ty * 4];
            u64 aa[4];
            aa[0] = pack2(av.x, av.x); aa[1] = pack2(av.y, av.y);
            aa[2] = pack2(av.z, av.z); aa[3] = pack2(av.w, av.w);
#pragma unroll
            for (int p = 0; p < 4; p++) {
                float2 bp = *(const float2*)&Bs[buf][k][2 * (tx + 16 * p)];
                u64 bb = pack2(bp.x, bp.y);
#pragma unroll
                for (int i = 0; i < 4; i++) acc[i][p] = fma2(aa[i], bb, acc[i][p]);
            }
        }
        __syncthreads();
    }

    if (j0 < DI) {
#pragma unroll
        for (int i = 0; i < 4; i++) {
            int l = l0 + ty * 4 + i;
#pragma unroll
            for (int p = 0; p < 4; p++) {
                float lo, hi; unpack2(acc[i][p], lo, hi);
                int j = j0 + 2 * (tx + 16 * p);
                float2 v; v.x = lo; v.y = hi;
                *(float2*)&g_xs[(b * LSEQ + l) * DI + j] = v;
            }
        }
    } else {
        // z half: silu + transposed store [d][l]
        float lv[4][4], hv[4][4];
#pragma unroll
        for (int i = 0; i < 4; i++)
#pragma unroll
            for (int p = 0; p < 4; p++) unpack2(acc[i][p], lv[i][p], hv[i][p]);
#pragma unroll
        for (int p = 0; p < 4; p++) {
            int jbase = (j0 - DI) + 2 * (tx + 16 * p);
            float4 v0, v1;
            v0.x = silu_f(lv[0][p]); v0.y = silu_f(lv[1][p]);
            v0.z = silu_f(lv[2][p]); v0.w = silu_f(lv[3][p]);
            v1.x = silu_f(hv[0][p]); v1.y = silu_f(hv[1][p]);
            v1.z = silu_f(hv[2][p]); v1.w = silu_f(hv[3][p]);
            *(float4*)&g_szT[(b * DI + jbase)     * LSEQ + l0 + ty * 4] = v0;
            *(float4*)&g_szT[(b * DI + jbase + 1) * LSEQ + l0 + ty * 4] = v1;
        }
    }
}

// ============================================================================
// K2: causal depthwise conv(4) + silu -> xc [d][l]; dbc = xc @ W_x;
//     dt = softplus(dbc[:, :16] @ W_dt + b_dt) -> [d][l];
//     B/C packed [l/4][s][l%4].
// ============================================================================
__global__ __launch_bounds__(256) void k_conv_proj(const float* __restrict__ convw,
                                                   const float* __restrict__ convb,
                                                   const float* __restrict__ Wx,
                                                   const float* __restrict__ Wdt,
                                                   const float* __restrict__ bdt) {
    __shared__ float xc_s[32][257];   // reused as dt staging in phase C
    __shared__ float dbc_s[32][49];
    const int t  = threadIdx.x;
    const int b  = blockIdx.x >> 7;
    const int l0 = (blockIdx.x & 127) * 32;

    // ---- Phase A: conv + silu (thread t owns channel d = t) ----
    {
        const int d = t;
        const float w0 = convw[d * 4 + 0], w1 = convw[d * 4 + 1];
        const float w2 = convw[d * 4 + 2], w3 = convw[d * 4 + 3];
        const float cb = convb[d];
        const float* pxs = g_xs + b * LSEQ * DI + d;
        float x0, x1, x2;
        if (l0 == 0) { x0 = x1 = x2 = 0.f; }
        else { x0 = pxs[(l0 - 3) * DI]; x1 = pxs[(l0 - 2) * DI]; x2 = pxs[(l0 - 1) * DI]; }
        for (int j = 0; j < 32; j++) {
            float x3 = pxs[(l0 + j) * DI];
            float c  = cb + w0 * x0 + w1 * x1 + w2 * x2 + w3 * x3;
            xc_s[j][d] = silu_f(c);
            x0 = x1; x1 = x2; x2 = x3;
        }
    }
    __syncthreads();

    // ---- transposed coalesced write of xc to [d][l] ----
    for (int i = t; i < 32 * DI; i += 256) {
        int d2 = i >> 5, r2 = i & 31;
        g_xc[(b * DI + d2) * LSEQ + l0 + r2] = xc_s[r2][d2];
    }

    // ---- Phase B: dbc[r][0..47] = xc[r] @ W_x ----
    {
        const int r = t & 31, g = t >> 5;   // g in 0..7, 6 cols each
        float acc[6];
#pragma unroll
        for (int jj = 0; jj < 6; jj++) acc[jj] = 0.f;
        const float* wbase = Wx + g * 6;
        for (int c = 0; c < DI; c++) {
            float xv = xc_s[r][c];
            const float2* wp = (const float2*)(wbase + c * 48);
            float2 wa = __ldg(wp), wb = __ldg(wp + 1), wc = __ldg(wp + 2);
            acc[0] = fmaf(xv, wa.x, acc[0]); acc[1] = fmaf(xv, wa.y, acc[1]);
            acc[2] = fmaf(xv, wb.x, acc[2]); acc[3] = fmaf(xv, wb.y, acc[3]);
            acc[4] = fmaf(xv, wc.x, acc[4]); acc[5] = fmaf(xv, wc.y, acc[5]);
        }
#pragma unroll
        for (int jj = 0; jj < 6; jj++) dbc_s[r][g * 6 + jj] = acc[jj];
    }
    __syncthreads();

    // ---- Phase C: dt = softplus(dbc[:, :16] @ W_dt + b_dt) into xc_s ----
    {
        const int d = t;
        float wdt[16];
#pragma unroll
        for (int k = 0; k < 16; k++) wdt[k] = Wdt[k * DI + d];
        const float bd = bdt[d];
        for (int r = 0; r < 32; r++) {
            float a = bd;
#pragma unroll
            for (int k = 0; k < 16; k++) a = fmaf(dbc_s[r][k], wdt[k], a);
            xc_s[r][d] = (a > 20.f) ? a : log1pf(__expf(a));
        }
    }
    __syncthreads();

    // ---- transposed coalesced write of dt to [d][l] ----
    for (int i = t; i < 32 * DI; i += 256) {
        int d2 = i >> 5, r2 = i & 31;
        g_dt[(b * DI + d2) * LSEQ + l0 + r2] = xc_s[r2][d2];
    }

    // ---- packed coalesced write of B / C: [l/4][s][l%4] ----
    {
        const int base = (b * LSEQ + l0) * DS;
        for (int i = t; i < 32 * DS; i += 256) {
            int g4 = i >> 6, s = (i >> 2) & 15, r2 = i & 3;
            int r = g4 * 4 + r2;
            g_Bm[base + i] = dbc_s[r][16 + s];
            g_Cm[base + i] = dbc_s[r][32 + s];
        }
    }
}

// ============================================================================
// K3a: per-chunk local scan -> S (final h with h0=0) and P = exp2(A2 * sum dt).
// Block = 16 d's x one chunk; working set staged in smem via one cp.async burst.
// ============================================================================
__global__ __launch_bounds__(256) void k_scan1(const float* __restrict__ Alog) {
    __shared__ __align__(16) float s_dt[16 * ROWP];
    __shared__ __align__(16) float s_xc[16 * ROWP];
    __shared__ __align__(16) float s_B [CHUNK * DS];

    const int t  = threadIdx.x;
    const int dg    = blockIdx.x & 15;
    const int chunk = (blockIdx.x >> 4) & (NC - 1);
    const int b     = blockIdx.x >> 9;
    const int d0 = dg * 16;
    const int l0 = chunk * CHUNK;

    const float* pdt_g = g_dt + (b * DI + d0) * LSEQ + l0;
    const float* pxc_g = g_xc + (b * DI + d0) * LSEQ + l0;
    const float* pB_g  = g_Bm + (b * LSEQ + l0) * DS;

#pragma unroll
    for (int i = t; i < 512 * 3; i += 256) {
        int r = i >> 9, j = i & 511;
        int w = j >> 5, j16 = (j & 31) * 4;
        if (r == 0)      cp_async16(&s_dt[w * ROWP + j16], pdt_g + w * LSEQ + j16);
        else if (r == 1) cp_async16(&s_xc[w * ROWP + j16], pxc_g + w * LSEQ + j16);
        else             cp_async16(&s_B[j * 4], pB_g + j * 4);
    }
    cp_commit(); cp_wait0();
    __syncthreads();

    const int w = t >> 4, s = t & 15;
    const int d = d0 + w;
    const float A2 = -__expf(Alog[d * DS + s]) * LOG2E;
    const float* sdt = s_dt + w * ROWP;
    const float* sxc = s_xc + w * ROWP;
    const float* sB  = s_B + s * 4;

    float h = 0.f, dts = 0.f;
#pragma unroll 8
    for (int l = 0; l < CHUNK; l += 4) {
        float4 dv = *(const float4*)(sdt + l);
        float4 xv = *(const float4*)(sxc + l);
        float4 Bv = *(const float4*)(sB + (l >> 2) * 64);
        h = fmaf(h, ex2f(dv.x * A2), dv.x * xv.x * Bv.x);
        h = fmaf(h, ex2f(dv.y * A2), dv.y * xv.y * Bv.y);
        h = fmaf(h, ex2f(dv.z * A2), dv.z * xv.z * Bv.z);
        h = fmaf(h, ex2f(dv.w * A2), dv.w * xv.w * Bv.w);
        dts += (dv.x + dv.y) + (dv.z + dv.w);
    }
    const int idx = ((b * DI + d) * NC + chunk) * DS + s;
    g_S[idx] = h;
    g_P[idx] = ex2f(A2 * dts);
}

// ============================================================================
// K3b: per-chunk scan with true initial state (self-stitched prefix).
// Block = 16 d's x one chunk; 40 KB smem staging. Butterfly reduction.
// Emits g_ymT = (y + xc*D) * silu(z)   in [b][d][l] layout (coalesced store).
// ============================================================================
__global__ __launch_bounds__(256) void k_scan3(const float* __restrict__ Alog,
                                               const float* __restrict__ Dvec) {
    __shared__ __align__(16) float s_dt[16 * ROWP];
    __shared__ __align__(16) float s_xc[16 * ROWP];
    __shared__ __align__(16) float s_sz[16 * ROWP];
    __shared__ __align__(16) float s_B [CHUNK * DS];
    __shared__ __align__(16) float s_C [CHUNK * DS];

    const int t  = threadIdx.x;
    const int dg    = blockIdx.x & 15;
    const int chunk = (blockIdx.x >> 4) & (NC - 1);
    const int b     = blockIdx.x >> 9;
    const int d0 = dg * 16;
    const int l0 = chunk * CHUNK;

    const float* pdt_g = g_dt  + (b * DI + d0) * LSEQ + l0;
    const float* pxc_g = g_xc  + (b * DI + d0) * LSEQ + l0;
    const float* psz_g = g_szT + (b * DI + d0) * LSEQ + l0;
    const float* pB_g  = g_Bm  + (b * LSEQ + l0) * DS;
    const float* pC_g  = g_Cm  + (b * LSEQ + l0) * DS;

#pragma unroll
    for (int i = t; i < 512 * 5; i += 256) {
        int r = i >> 9, j = i & 511;
        int w = j >> 5, j16 = (j & 31) * 4;
        if (r == 0)      cp_async16(&s_dt[w * ROWP + j16], pdt_g + w * LSEQ + j16);
        else if (r == 1) cp_async16(&s_xc[w * ROWP + j16], pxc_g + w * LSEQ + j16);
        else if (r == 2) cp_async16(&s_sz[w * ROWP + j16], psz_g + w * LSEQ + j16);
        else if (r == 3) cp_async16(&s_B[j * 4], pB_g + j * 4);
        else             cp_async16(&s_C[j * 4], pC_g + j * 4);
    }
    cp_commit();

    const int w = t >> 4, s = t & 15;
    const int d = d0 + w;
    const float A2 = -__expf(Alog[d * DS + s]) * LOG2E;
    const float Dd = Dvec[d];
    float*       pyT = g_ymT + (b * DI + d) * LSEQ + l0;

    // ---- self-stitched prefix (overlaps with the cp.async fill) ----
    float h = 0.f;
    {
        const int pbase = (b * DI + d) * NC * DS + s;
#pragma unroll
        for (int c = 0; c < NC - 1; c++) {
            if (c < chunk) h = fmaf(g_P[pbase + c * DS], h, g_S[pbase + c * DS]);
        }
    }

    cp_wait0();
    __syncthreads();

    const float* sdt = s_dt + w * ROWP;
    const float* sxc = s_xc + w * ROWP;
    const float* ssz = s_sz + w * ROWP;
    const float* sB  = s_B + s * 4;
    const float* sC  = s_C + s * 4;

    for (int l = 0; l < CHUNK; l += 16) {
        float wv[16];
#pragma unroll
        for (int g = 0; g < 4; g++) {
            float4 dv = *(const float4*)(sdt + l + g * 4);
            float4 xv = *(const float4*)(sxc + l + g * 4);
            float4 Bv = *(const float4*)(sB + ((l >> 2) + g) * 64);
            float4 Cv = *(const float4*)(sC + ((l >> 2) + g) * 64);
            h = fmaf(h, ex2f(dv.x * A2), dv.x * xv.x * Bv.x); wv[g * 4 + 0] = h * Cv.x;
            h = fmaf(h, ex2f(dv.y * A2), dv.y * xv.y * Bv.y); wv[g * 4 + 1] = h * Cv.y;
            h = fmaf(h, ex2f(dv.z * A2), dv.z * xv.z * Bv.z); wv[g * 4 + 2] = h * Cv.z;
            h = fmaf(h, ex2f(dv.w * A2), dv.w * xv.w * Bv.w); wv[g * 4 + 3] = h * Cv.w;
        }
        float y  = hreduce16(wv, s);
        float xs = sxc[l + s];
        float zs = ssz[l + s];
        pyT[l + s] = fmaf(xs, Dd, y) * zs;
    }
}

// ============================================================================
// K4: out-projection GEMM.  out[b,c,l] = sum_d ymT[b,d,l] * W_out[d,c]
// NEW: 64(c) x 64(l) tiles -> 512 blocks (3.46/SM, was 1.73).
// Thread = 4(c) x 4(l) micro-tile; inner loop 2xLDS.128 + 8 FFMA2.
// ============================================================================
__global__ __launch_bounds__(256) void k_outproj(const float* __restrict__ Wout,
                                                 float* __restrict__ out) {
    __shared__ float As[2][16][64];
    __shared__ float Bs[2][16][68];
    const int t  = threadIdx.x;
    const int l0 = blockIdx.x * 64, c0 = blockIdx.y * 64, b = blockIdx.z;
    const int ty = t >> 4, tx = t & 15;

    u64 acc[4][2];
#pragma unroll
    for (int i = 0; i < 4; i++) { acc[i][0] = 0ull; acc[i][1] = 0ull; }

    const float* ymb = g_ymT + b * DI * LSEQ;
    const int kk = t >> 4, p4 = (t & 15) * 4;
    auto pref = [&](int tile, int buf) {
        cp_async16(&As[buf][kk][p4], Wout + (tile * 16 + kk) * DM + c0 + p4);
        cp_async16(&Bs[buf][kk][p4], ymb + (tile * 16 + kk) * LSEQ + l0 + p4);
    };

    pref(0, 0); cp_commit();

    for (int it = 0; it < 16; it++) {
        const int buf = it & 1;
        cp_wait0();
        __syncthreads();
        if (it + 1 < 16) { pref(it + 1, buf ^ 1); cp_commit(); }
#pragma unroll
        for (int k = 0; k < 16; k++) {
            float4 av = *(const float4*)&As[buf][k][ty * 4];
            float4 bv = *(const float4*)&Bs[buf][k][tx * 4];
            u64 bb0 = pack2(bv.x, bv.y);
            u64 bb1 = pack2(bv.z, bv.w);
            u64 aa0 = pack2(av.x, av.x);
            u64 aa1 = pack2(av.y, av.y);
            u64 aa2 = pack2(av.z, av.z);
            u64 aa3 = pack2(av.w, av.w);
            acc[0][0] = fma2(aa0, bb0, acc[0][0]);
            acc[0][1] = fma2(aa0, bb1, acc[0][1]);
            acc[1][0] = fma2(aa1, bb0, acc[1][0]);
            acc[1][1] = fma2(aa1, bb1, acc[1][1]);
            acc[2][0] = fma2(aa2, bb0, acc[2][0]);
            acc[2][1] = fma2(aa2, bb1, acc[2][1]);
            acc[3][0] = fma2(aa3, bb0, acc[3][0]);
            acc[3][1] = fma2(aa3, bb1, acc[3][1]);
        }
        __syncthreads();
    }

#pragma unroll
    for (int i = 0; i < 4; i++) {
        int c = c0 + ty * 4 + i;
        float4 v;
        unpack2(acc[i][0], v.x, v.y);
        unpack2(acc[i][1], v.z, v.w);
        *(float4*)&out[(b * DM + c) * LSEQ + l0 + tx * 4] = v;
    }
}

// ============================================================================
extern "C" void kernel_launch(void* const* d_in, const int* in_sizes, int n_in,
                              void* d_out, int out_size) {
    (void)in_sizes; (void)n_in; (void)out_size;
    const float* x     = (const float*)d_in[0];
    const float* Win   = (const float*)d_in[1];
    const float* convw = (const float*)d_in[2];
    const float* convb = (const float*)d_in[3];
    const float* Wx    = (const float*)d_in[4];
    const float* Wdt   = (const float*)d_in[5];
    const float* bdt   = (const float*)d_in[6];
    const float* Alog  = (const float*)d_in[7];
    const float* Dvec  = (const float*)d_in[8];
    const float* Wout  = (const float*)d_in[9];
    float* out = (float*)d_out;

    k_inproj   <<<dim3(64, 4, 2), 256>>>(x, Win);
    k_conv_proj<<<256, 256>>>(convw, convb, Wx, Wdt, bdt);
    k_scan1    <<<1024, 256>>>(Alog);
    k_scan3    <<<1024, 256>>>(Alog, Dvec);
    k_outproj  <<<dim3(64, 4, 2), 256>>>(Wout, out);
}

// round 16
// speedup vs baseline: 1.4181x; 1.0080x over previous
#include <cuda_runtime.h>

#define BSZ  2
#define DM   256
#define LSEQ 4096
#define DI   256
#define DS   16
#define NC   32
#define CHUNK (LSEQ / NC)   // 128
#define ROWP 132            // padded smem row stride (floats)

// ---------------- scratch (static device globals; no runtime alloc) ----------
__device__ float g_xs [BSZ*LSEQ*DI];   // in-proj left half          [b][l][d]
__device__ float g_szT[BSZ*DI*LSEQ];   // silu(z) TRANSPOSED         [b][d][l]
__device__ float g_xc [BSZ*DI*LSEQ];   // conv+silu output           [b][d][l]
__device__ float g_dt [BSZ*DI*LSEQ];   // softplus(dt)               [b][d][l]
__device__ float g_Bm [BSZ*LSEQ*DS];   // B packed  [b][l/4][s][l%4]
__device__ float g_Cm [BSZ*LSEQ*DS];   // C packed  [b][l/4][s][l%4]
__device__ float g_ymT[BSZ*DI*LSEQ];   // (y + xc*D)*silu(z)         [b][d][l]
__device__ float g_S  [BSZ*DI*NC*DS];  // chunk-final local states
__device__ float g_P  [BSZ*DI*NC*DS];  // chunk decay products

typedef unsigned long long u64;

__device__ __forceinline__ u64 pack2(float lo, float hi) {
    u64 r; asm("mov.b64 %0, {%1, %2};" : "=l"(r) : "f"(lo), "f"(hi)); return r;
}
__device__ __forceinline__ void unpack2(u64 v, float& lo, float& hi) {
    asm("mov.b64 {%0, %1}, %2;" : "=f"(lo), "=f"(hi) : "l"(v));
}
__device__ __forceinline__ u64 fma2(u64 a, u64 b, u64 c) {
    u64 d; asm("fma.rn.f32x2 %0, %1, %2, %3;" : "=l"(d) : "l"(a), "l"(b), "l"(c)); return d;
}
__device__ __forceinline__ float silu_f(float v) { return v / (1.f + __expf(-v)); }
__device__ __forceinline__ float ex2f(float v) {
    float r; asm("ex2.approx.ftz.f32 %0, %1;" : "=f"(r) : "f"(v)); return r;
}
#define LOG2E 1.4426950408889634f

__device__ __forceinline__ void cp_async16(void* smem, const void* g) {
    unsigned sa = (unsigned)__cvta_generic_to_shared(smem);
    asm volatile("cp.async.cg.shared.global [%0], [%1], 16;\n" :: "r"(sa), "l"(g));
}
__device__ __forceinline__ void cp_commit() {
    asm volatile("cp.async.commit_group;\n");
}
__device__ __forceinline__ void cp_wait0() {
    asm volatile("cp.async.wait_group 0;\n");
}

// Exchange-halving butterfly: reduce 16 independent sums across 16 lanes.
__device__ __forceinline__ float hreduce16(float* w, int s) {
#pragma unroll
    for (int i = 0; i < 8; i++) {
        float snd = (s & 8) ? w[i] : w[i + 8];
        float kp  = (s & 8) ? w[i + 8] : w[i];
        w[i] = kp + __shfl_xor_sync(0xffffffffu, snd, 8, 16);
    }
#pragma unroll
    for (int i = 0; i < 4; i++) {
        float snd = (s & 4) ? w[i] : w[i + 4];
        float kp  = (s & 4) ? w[i + 4] : w[i];
        w[i] = kp + __shfl_xor_sync(0xffffffffu, snd, 4, 16);
    }
#pragma unroll
    for (int i = 0; i < 2; i++) {
        float snd = (s & 2) ? w[i] : w[i + 2];
        float kp  = (s & 2) ? w[i + 2] : w[i];
        w[i] = kp + __shfl_xor_sync(0xffffffffu, snd, 2, 16);
    }
    {
        float snd = (s & 1) ? w[0] : w[1];
        float kp  = (s & 1) ? w[1] : w[0];
        w[0] = kp + __shfl_xor_sync(0xffffffffu, snd, 1, 16);
    }
    return w[0];
}

// ============================================================================
// K1: in-projection GEMM.  out[b,l,j] = sum_c x[b,c,l] * W_in[c,j]
// 64(l) x 128(j) tiles, K-tiles of 32 (8 iterations), cp.async double-buffered.
// Same thread mapping / inner body as the 150.0 baseline.
// ============================================================================
__global__ __launch_bounds__(256) void k_inproj(const float* __restrict__ x,
                                                const float* __restrict__ Win) {
    __shared__ float As[2][32][64];    // 16 KB
    __shared__ float Bs[2][32][128];   // 32 KB  (total 48 KB exactly)
    const int t  = threadIdx.x;
    const int l0 = blockIdx.x * 64, j0 = blockIdx.y * 128, b = blockIdx.z;
    const int ty = t >> 4, tx = t & 15;
    const float* xb = x + b * DM * LSEQ;

    u64 acc[4][4];
#pragma unroll
    for (int i = 0; i < 4; i++)
#pragma unroll
        for (int p = 0; p < 4; p++) acc[i][p] = 0ull;

    auto pref = [&](int tile, int buf) {
#pragma unroll
        for (int i = 0; i < 2; i++) {
            int idx = t + i * 256;
            int kk = idx >> 4, ja = (idx & 15) * 4;
            cp_async16(&As[buf][kk][ja], xb + (tile * 32 + kk) * LSEQ + l0 + ja);
        }
#pragma unroll
        for (int i = 0; i < 4; i++) {
            int idx = t + i * 256;
            int kb = idx >> 5, jb = (idx & 31) * 4;
            cp_async16(&Bs[buf][kb][jb], Win + (tile * 32 + kb) * (2 * DI) + j0 + jb);
        }
    };

    pref(0, 0); cp_commit();

    for (int it = 0; it < 8; it++) {
        const int buf = it & 1;
        cp_wait0();
        __syncthreads();
        if (it + 1 < 8) { pref(it + 1, buf ^ 1); cp_commit(); }
#pragma unroll
        for (int k = 0; k < 32; k++) {
            float4 av = *(const float4*)&As[buf][k][ty * 4];
            u64 aa[4];
            aa[0] = pack2(av.x, av.x); aa[1] = pack2(av.y, av.y);
            aa[2] = pack2(av.z, av.z); aa[3] = pack2(av.w, av.w);
#pragma unroll
            for (int p = 0; p < 4; p++) {
                float2 bp = *(const float2*)&Bs[buf][k][2 * (tx + 16 * p)];
                u64 bb = pack2(bp.x, bp.y);
#pragma unroll
                for (int i = 0; i < 4; i++) acc[i][p] = fma2(aa[i], bb, acc[i][p]);
            }
        }
        __syncthreads();
    }

    if (j0 < DI) {
#pragma unroll
        for (int i = 0; i < 4; i++) {
            int l = l0 + ty * 4 + i;
#pragma unroll
            for (int p = 0; p < 4; p++) {
                float lo, hi; unpack2(acc[i][p], lo, hi);
                int j = j0 + 2 * (tx + 16 * p);
                float2 v; v.x = lo; v.y = hi;
                *(float2*)&g_xs[(b * LSEQ + l) * DI + j] = v;
            }
        }
    } else {
        // z half: silu + transposed store [d][l]
        float lv[4][4], hv[4][4];
#pragma unroll
        for (int i = 0; i < 4; i++)
#pragma unroll
            for (int p = 0; p < 4; p++) unpack2(acc[i][p], lv[i][p], hv[i][p]);
#pragma unroll
        for (int p = 0; p < 4; p++) {
            int jbase = (j0 - DI) + 2 * (tx + 16 * p);
            float4 v0, v1;
            v0.x = silu_f(lv[0][p]); v0.y = silu_f(lv[1][p]);
            v0.z = silu_f(lv[2][p]); v0.w = silu_f(lv[3][p]);
            v1.x = silu_f(hv[0][p]); v1.y = silu_f(hv[1][p]);
            v1.z = silu_f(hv[2][p]); v1.w = silu_f(hv[3][p]);
            *(float4*)&g_szT[(b * DI + jbase)     * LSEQ + l0 + ty * 4] = v0;
            *(float4*)&g_szT[(b * DI + jbase + 1) * LSEQ + l0 + ty * 4] = v1;
        }
    }
}

// ============================================================================
// K2: causal depthwise conv(4) + silu -> xc [d][l]; dbc = xc @ W_x;
//     dt = softplus(dbc[:, :16] @ W_dt + b_dt) -> [d][l];
//     B/C packed [l/4][s][l%4].   (verbatim from the 150.0 baseline)
// ============================================================================
__global__ __launch_bounds__(256) void k_conv_proj(const float* __restrict__ convw,
                                                   const float* __restrict__ convb,
                                                   const float* __restrict__ Wx,
                                                   const float* __restrict__ Wdt,
                                                   const float* __restrict__ bdt) {
    __shared__ float xc_s[32][257];   // reused as dt staging in phase C
    __shared__ float dbc_s[32][49];
    const int t  = threadIdx.x;
    const int b  = blockIdx.x >> 7;
    const int l0 = (blockIdx.x & 127) * 32;

    // ---- Phase A: conv + silu (thread t owns channel d = t) ----
    {
        const int d = t;
        const float w0 = convw[d * 4 + 0], w1 = convw[d * 4 + 1];
        const float w2 = convw[d * 4 + 2], w3 = convw[d * 4 + 3];
        const float cb = convb[d];
        const float* pxs = g_xs + b * LSEQ * DI + d;
        float x0, x1, x2;
        if (l0 == 0) { x0 = x1 = x2 = 0.f; }
        else { x0 = pxs[(l0 - 3) * DI]; x1 = pxs[(l0 - 2) * DI]; x2 = pxs[(l0 - 1) * DI]; }
        for (int j = 0; j < 32; j++) {
            float x3 = pxs[(l0 + j) * DI];
            float c  = cb + w0 * x0 + w1 * x1 + w2 * x2 + w3 * x3;
            xc_s[j][d] = silu_f(c);
            x0 = x1; x1 = x2; x2 = x3;
        }
    }
    __syncthreads();

    // ---- transposed coalesced write of xc to [d][l] ----
    for (int i = t; i < 32 * DI; i += 256) {
        int d2 = i >> 5, r2 = i & 31;
        g_xc[(b * DI + d2) * LSEQ + l0 + r2] = xc_s[r2][d2];
    }

    // ---- Phase B: dbc[r][0..47] = xc[r] @ W_x ----
    {
        const int r = t & 31, g = t >> 5;   // g in 0..7, 6 cols each
        float acc[6];
#pragma unroll
        for (int jj = 0; jj < 6; jj++) acc[jj] = 0.f;
        const float* wbase = Wx + g * 6;
        for (int c = 0; c < DI; c++) {
            float xv = xc_s[r][c];
            const float2* wp = (const float2*)(wbase + c * 48);
            float2 wa = __ldg(wp), wb = __ldg(wp + 1), wc = __ldg(wp + 2);
            acc[0] = fmaf(xv, wa.x, acc[0]); acc[1] = fmaf(xv, wa.y, acc[1]);
            acc[2] = fmaf(xv, wb.x, acc[2]); acc[3] = fmaf(xv, wb.y, acc[3]);
            acc[4] = fmaf(xv, wc.x, acc[4]); acc[5] = fmaf(xv, wc.y, acc[5]);
        }
#pragma unroll
        for (int jj = 0; jj < 6; jj++) dbc_s[r][g * 6 + jj] = acc[jj];
    }
    __syncthreads();

    // ---- Phase C: dt = softplus(dbc[:, :16] @ W_dt + b_dt) into xc_s ----
    {
        const int d = t;
        float wdt[16];
#pragma unroll
        for (int k = 0; k < 16; k++) wdt[k] = Wdt[k * DI + d];
        const float bd = bdt[d];
        for (int r = 0; r < 32; r++) {
            float a = bd;
#pragma unroll
            for (int k = 0; k < 16; k++) a = fmaf(dbc_s[r][k], wdt[k], a);
            xc_s[r][d] = (a > 20.f) ? a : log1pf(__expf(a));
        }
    }
    __syncthreads();

    // ---- transposed coalesced write of dt to [d][l] ----
    for (int i = t; i < 32 * DI; i += 256) {
        int d2 = i >> 5, r2 = i & 31;
        g_dt[(b * DI + d2) * LSEQ + l0 + r2] = xc_s[r2][d2];
    }

    // ---- packed coalesced write of B / C: [l/4][s][l%4] ----
    {
        const int base = (b * LSEQ + l0) * DS;
        for (int i = t; i < 32 * DS; i += 256) {
            int g4 = i >> 6, s = (i >> 2) & 15, r2 = i & 3;
            int r = g4 * 4 + r2;
            g_Bm[base + i] = dbc_s[r][16 + s];
            g_Cm[base + i] = dbc_s[r][32 + s];
        }
    }
}

// ============================================================================
// K3a: per-chunk local scan -> S (final h with h0=0) and P = exp2(A2 * sum dt).
// Block = 16 d's x one chunk; working set staged in smem via one cp.async burst.
// (verbatim from the 150.0 baseline)
// ============================================================================
__global__ __launch_bounds__(256) void k_scan1(const float* __restrict__ Alog) {
    __shared__ __align__(16) float s_dt[16 * ROWP];
    __shared__ __align__(16) float s_xc[16 * ROWP];
    __shared__ __align__(16) float s_B [CHUNK * DS];

    const int t  = threadIdx.x;
    const int dg    = blockIdx.x & 15;
    const int chunk = (blockIdx.x >> 4) & (NC - 1);
    const int b     = blockIdx.x >> 9;
    const int d0 = dg * 16;
    const int l0 = chunk * CHUNK;

    const float* pdt_g = g_dt + (b * DI + d0) * LSEQ + l0;
    const float* pxc_g = g_xc + (b * DI + d0) * LSEQ + l0;
    const float* pB_g  = g_Bm + (b * LSEQ + l0) * DS;

#pragma unroll
    for (int i = t; i < 512 * 3; i += 256) {
        int r = i >> 9, j = i & 511;
        int w = j >> 5, j16 = (j & 31) * 4;
        if (r == 0)      cp_async16(&s_dt[w * ROWP + j16], pdt_g + w * LSEQ + j16);
        else if (r == 1) cp_async16(&s_xc[w * ROWP + j16], pxc_g + w * LSEQ + j16);
        else             cp_async16(&s_B[j * 4], pB_g + j * 4);
    }
    cp_commit(); cp_wait0();
    __syncthreads();

    const int w = t >> 4, s = t & 15;
    const int d = d0 + w;
    const float A2 = -__expf(Alog[d * DS + s]) * LOG2E;
    const float* sdt = s_dt + w * ROWP;
    const float* sxc = s_xc + w * ROWP;
    const float* sB  = s_B + s * 4;

    float h = 0.f, dts = 0.f;
#pragma unroll 8
    for (int l = 0; l < CHUNK; l += 4) {
        float4 dv = *(const float4*)(sdt + l);
        float4 xv = *(const float4*)(sxc + l);
        float4 Bv = *(const float4*)(sB + (l >> 2) * 64);
        h = fmaf(h, ex2f(dv.x * A2), dv.x * xv.x * Bv.x);
        h = fmaf(h, ex2f(dv.y * A2), dv.y * xv.y * Bv.y);
        h = fmaf(h, ex2f(dv.z * A2), dv.z * xv.z * Bv.z);
        h = fmaf(h, ex2f(dv.w * A2), dv.w * xv.w * Bv.w);
        dts += (dv.x + dv.y) + (dv.z + dv.w);
    }
    const int idx = ((b * DI + d) * NC + chunk) * DS + s;
    g_S[idx] = h;
    g_P[idx] = ex2f(A2 * dts);
}

// ============================================================================
// K3b: per-chunk scan with true initial state (self-stitched prefix).
// Block = 16 d's x one chunk; 40 KB smem staging. Butterfly reduction.
// Emits g_ymT = (y + xc*D) * silu(z)   in [b][d][l] layout (coalesced store).
// (verbatim from the 150.0 baseline)
// ============================================================================
__global__ __launch_bounds__(256) void k_scan3(const float* __restrict__ Alog,
                                               const float* __restrict__ Dvec) {
    __shared__ __align__(16) float s_dt[16 * ROWP];
    __shared__ __align__(16) float s_xc[16 * ROWP];
    __shared__ __align__(16) float s_sz[16 * ROWP];
    __shared__ __align__(16) float s_B [CHUNK * DS];
    __shared__ __align__(16) float s_C [CHUNK * DS];

    const int t  = threadIdx.x;
    const int dg    = blockIdx.x & 15;
    const int chunk = (blockIdx.x >> 4) & (NC - 1);
    const int b     = blockIdx.x >> 9;
    const int d0 = dg * 16;
    const int l0 = chunk * CHUNK;

    const float* pdt_g = g_dt  + (b * DI + d0) * LSEQ + l0;
    const float* pxc_g = g_xc  + (b * DI + d0) * LSEQ + l0;
    const float* psz_g = g_szT + (b * DI + d0) * LSEQ + l0;
    const float* pB_g  = g_Bm  + (b * LSEQ + l0) * DS;
    const float* pC_g  = g_Cm  + (b * LSEQ + l0) * DS;

#pragma unroll
    for (int i = t; i < 512 * 5; i += 256) {
        int r = i >> 9, j = i & 511;
        int w = j >> 5, j16 = (j & 31) * 4;
        if (r == 0)      cp_async16(&s_dt[w * ROWP + j16], pdt_g + w * LSEQ + j16);
        else if (r == 1) cp_async16(&s_xc[w * ROWP + j16], pxc_g + w * LSEQ + j16);
        else if (r == 2) cp_async16(&s_sz[w * ROWP + j16], psz_g + w * LSEQ + j16);
        else if (r == 3) cp_async16(&s_B[j * 4], pB_g + j * 4);
        else             cp_async16(&s_C[j * 4], pC_g + j * 4);
    }
    cp_commit();

    const int w = t >> 4, s = t & 15;
    const int d = d0 + w;
    const float A2 = -__expf(Alog[d * DS + s]) * LOG2E;
    const float Dd = Dvec[d];
    float*       pyT = g_ymT + (b * DI + d) * LSEQ + l0;

    // ---- self-stitched prefix (overlaps with the cp.async fill) ----
    float h = 0.f;
    {
        const int pbase = (b * DI + d) * NC * DS + s;
#pragma unroll
        for (int c = 0; c < NC - 1; c++) {
            if (c < chunk) h = fmaf(g_P[pbase + c * DS], h, g_S[pbase + c * DS]);
        }
    }

    cp_wait0();
    __syncthreads();

    const float* sdt = s_dt + w * ROWP;
    const float* sxc = s_xc + w * ROWP;
    const float* ssz = s_sz + w * ROWP;
    const float* sB  = s_B + s * 4;
    const float* sC  = s_C + s * 4;

    for (int l = 0; l < CHUNK; l += 16) {
        float wv[16];
#pragma unroll
        for (int g = 0; g < 4; g++) {
            float4 dv = *(const float4*)(sdt + l + g * 4);
            float4 xv = *(const float4*)(sxc + l + g * 4);
            float4 Bv = *(const float4*)(sB + ((l >> 2) + g) * 64);
            float4 Cv = *(const float4*)(sC + ((l >> 2) + g) * 64);
            h = fmaf(h, ex2f(dv.x * A2), dv.x * xv.x * Bv.x); wv[g * 4 + 0] = h * Cv.x;
            h = fmaf(h, ex2f(dv.y * A2), dv.y * xv.y * Bv.y); wv[g * 4 + 1] = h * Cv.y;
            h = fmaf(h, ex2f(dv.z * A2), dv.z * xv.z * Bv.z); wv[g * 4 + 2] = h * Cv.z;
            h = fmaf(h, ex2f(dv.w * A2), dv.w * xv.w * Bv.w); wv[g * 4 + 3] = h * Cv.w;
        }
        float y  = hreduce16(wv, s);
        float xs = sxc[l + s];
        float zs = ssz[l + s];
        pyT[l + s] = fmaf(xs, Dd, y) * zs;
    }
}

// ============================================================================
// K4: out-projection GEMM.  out[b,c,l] = sum_d ymT[b,d,l] * W_out[d,c]
// 64(c) x 64(l) tiles, K-tiles of 32 (8 iterations) -> 512 blocks, 32 KB smem.
// ============================================================================
__global__ __launch_bounds__(256) void k_outproj(const float* __restrict__ Wout,
                                                 float* __restrict__ out) {
    __shared__ float As[2][32][64];   // 16 KB
    __shared__ float Bs[2][32][64];   // 16 KB
    const int t  = threadIdx.x;
    const int l0 = blockIdx.x * 64, c0 = blockIdx.y * 64, b = blockIdx.z;
    const int ty = t >> 4, tx = t & 15;

    u64 acc[4][2];
#pragma unroll
    for (int i = 0; i < 4; i++) { acc[i][0] = 0ull; acc[i][1] = 0ull; }

    const float* ymb = g_ymT + b * DI * LSEQ;
    auto pref = [&](int tile, int buf) {
#pragma unroll
        for (int i = 0; i < 2; i++) {
            int idx = t + i * 256;
            int kk = idx >> 4, ja = (idx & 15) * 4;
            cp_async16(&As[buf][kk][ja], Wout + (tile * 32 + kk) * DM + c0 + ja);
            cp_async16(&Bs[buf][kk][ja], ymb + (tile * 32 + kk) * LSEQ + l0 + ja);
        }
    };

    pref(0, 0); cp_commit();

    for (int it = 0; it < 8; it++) {
        const int buf = it & 1;
        cp_wait0();
        __syncthreads();
        if (it + 1 < 8) { pref(it + 1, buf ^ 1); cp_commit(); }
#pragma unroll
        for (int k = 0; k < 32; k++) {
            float4 av = *(const float4*)&As[buf][k][ty * 4];
            float4 bv = *(const float4*)&Bs[buf][k][tx * 4];
            u64 bb0 = pack2(bv.x, bv.y);
            u64 bb1 = pack2(bv.z, bv.w);
            u64 aa0 = pack2(av.x, av.x);
            u64 aa1 = pack2(av.y, av.y);
            u64 aa2 = pack2(av.z, av.z);
            u64 aa3 = pack2(av.w, av.w);
            acc[0][0] = fma2(aa0, bb0, acc[0][0]);
            acc[0][1] = fma2(aa0, bb1, acc[0][1]);
            acc[1][0] = fma2(aa1, bb0, acc[1][0]);
            acc[1][1] = fma2(aa1, bb1, acc[1][1]);
            acc[2][0] = fma2(aa2, bb0, acc[2][0]);
            acc[2][1] = fma2(aa2, bb1, acc[2][1]);
            acc[3][0] = fma2(aa3, bb0, acc[3][0]);
            acc[3][1] = fma2(aa3, bb1, acc[3][1]);
        }
        __syncthreads();
    }

#pragma unroll
    for (int i = 0; i < 4; i++) {
        int c = c0 + ty * 4 + i;
        float4 v;
        unpack2(acc[i][0], v.x, v.y);
        unpack2(acc[i][1], v.z, v.w);
        *(float4*)&out[(b * DM + c) * LSEQ + l0 + tx * 4] = v;
    }
}

// ============================================================================
extern "C" void kernel_launch(void* const* d_in, const int* in_sizes, int n_in,
                              void* d_out, int out_size) {
    (void)in_sizes; (void)n_in; (void)out_size;
    const float* x     = (const float*)d_in[0];
    const float* Win   = (const float*)d_in[1];
    const float* convw = (const float*)d_in[2];
    const float* convb = (const float*)d_in[3];
    const float* Wx    = (const float*)d_in[4];
    const float* Wdt   = (const float*)d_in[5];
    const float* bdt   = (const float*)d_in[6];
    const float* Alog  = (const float*)d_in[7];
    const float* Dvec  = (const float*)d_in[8];
    const float* Wout  = (const float*)d_in[9];
    float* out = (float*)d_out;

    k_inproj   <<<dim3(64, 4, 2), 256>>>(x, Win);
    k_conv_proj<<<256, 256>>>(convw, convb, Wx, Wdt, bdt);
    k_scan1    <<<1024, 256>>>(Alog);
    k_scan3    <<<1024, 256>>>(Alog, Dvec);
    k_outproj  <<<dim3(64, 4, 2), 256>>>(Wout, out);
}

// round 17
// speedup vs baseline: 1.4393x; 1.0149x over previous
#include <cuda_runtime.h>

#define BSZ  2
#define DM   256
#define LSEQ 4096
#define DI   256
#define DS   16
#define NC   32
#define CHUNK (LSEQ / NC)   // 128
#define ROWP 132            // padded smem row stride (floats)

// ---------------- scratch (static device globals; no runtime alloc) ----------
__device__ float g_xs [BSZ*LSEQ*DI];   // in-proj left half          [b][l][d]
__device__ float g_szT[BSZ*DI*LSEQ];   // silu(z) TRANSPOSED         [b][d][l]
__device__ float g_xc [BSZ*DI*LSEQ];   // conv+silu output           [b][d][l]
__device__ float g_dt [BSZ*DI*LSEQ];   // softplus(dt)               [b][d][l]
__device__ float g_Bm [BSZ*LSEQ*DS];   // B packed  [b][l/4][s][l%4]
__device__ float g_Cm [BSZ*LSEQ*DS];   // C packed  [b][l/4][s][l%4]
__device__ float g_ymT[BSZ*DI*LSEQ];   // (y + xc*D)*silu(z)         [b][d][l]
__device__ float g_S  [BSZ*DI*NC*DS];  // chunk-final local states
__device__ float g_P  [BSZ*DI*NC*DS];  // chunk decay products

typedef unsigned long long u64;

__device__ __forceinline__ u64 pack2(float lo, float hi) {
    u64 r; asm("mov.b64 %0, {%1, %2};" : "=l"(r) : "f"(lo), "f"(hi)); return r;
}
__device__ __forceinline__ void unpack2(u64 v, float& lo, float& hi) {
    asm("mov.b64 {%0, %1}, %2;" : "=f"(lo), "=f"(hi) : "l"(v));
}
__device__ __forceinline__ u64 fma2(u64 a, u64 b, u64 c) {
    u64 d; asm("fma.rn.f32x2 %0, %1, %2, %3;" : "=l"(d) : "l"(a), "l"(b), "l"(c)); return d;
}
__device__ __forceinline__ float silu_f(float v) { return v / (1.f + __expf(-v)); }
__device__ __forceinline__ float ex2f(float v) {
    float r; asm("ex2.approx.ftz.f32 %0, %1;" : "=f"(r) : "f"(v)); return r;
}
#define LOG2E 1.4426950408889634f

__device__ __forceinline__ void cp_async16(void* smem, const void* g) {
    unsigned sa = (unsigned)__cvta_generic_to_shared(smem);
    asm volatile("cp.async.cg.shared.global [%0], [%1], 16;\n" :: "r"(sa), "l"(g));
}
__device__ __forceinline__ void cp_commit() {
    asm volatile("cp.async.commit_group;\n");
}
__device__ __forceinline__ void cp_wait0() {
    asm volatile("cp.async.wait_group 0;\n");
}

// Exchange-halving butterfly: reduce 16 independent sums across 16 lanes.
__device__ __forceinline__ float hreduce16(float* w, int s) {
#pragma unroll
    for (int i = 0; i < 8; i++) {
        float snd = (s & 8) ? w[i] : w[i + 8];
        float kp  = (s & 8) ? w[i + 8] : w[i];
        w[i] = kp + __shfl_xor_sync(0xffffffffu, snd, 8, 16);
    }
#pragma unroll
    for (int i = 0; i < 4; i++) {
        float snd = (s & 4) ? w[i] : w[i + 4];
        float kp  = (s & 4) ? w[i + 4] : w[i];
        w[i] = kp + __shfl_xor_sync(0xffffffffu, snd, 4, 16);
    }
#pragma unroll
    for (int i = 0; i < 2; i++) {
        float snd = (s & 2) ? w[i] : w[i + 2];
        float kp  = (s & 2) ? w[i + 2] : w[i];
        w[i] = kp + __shfl_xor_sync(0xffffffffu, snd, 2, 16);
    }
    {
        float snd = (s & 1) ? w[0] : w[1];
        float kp  = (s & 1) ? w[1] : w[0];
        w[0] = kp + __shfl_xor_sync(0xffffffffu, snd, 1, 16);
    }
    return w[0];
}

// ============================================================================
// K1: in-projection GEMM.  out[b,l,j] = sum_c x[b,c,l] * W_in[c,j]
// 64(l) x 128(j) tiles, K-tiles of 16, cp.async double-buffered. (R11 exact)
// ============================================================================
__global__ __launch_bounds__(256) void k_inproj(const float* __restrict__ x,
                                                const float* __restrict__ Win) {
    __shared__ float As[2][16][64];
    __shared__ float Bs[2][16][132];
    const int t  = threadIdx.x;
    const int l0 = blockIdx.x * 64, j0 = blockIdx.y * 128, b = blockIdx.z;
    const int ty = t >> 4, tx = t & 15;
    const float* xb = x + b * DM * LSEQ;

    u64 acc[4][4];
#pragma unroll
    for (int i = 0; i < 4; i++)
#pragma unroll
        for (int p = 0; p < 4; p++) acc[i][p] = 0ull;

    const int ka = t >> 4, ja = (t & 15) * 4;
    auto pref = [&](int tile, int buf) {
        cp_async16(&As[buf][ka][ja], xb + (tile * 16 + ka) * LSEQ + l0 + ja);
#pragma unroll
        for (int i = 0; i < 2; i++) {
            int idx = t + i * 256;
            int kb = idx >> 5, jb = (idx & 31) * 4;
            cp_async16(&Bs[buf][kb][jb], Win + (tile * 16 + kb) * (2 * DI) + j0 + jb);
        }
    };

    pref(0, 0); cp_commit();

    for (int it = 0; it < 16; it++) {
        const int buf = it & 1;
        cp_wait0();
        __syncthreads();
        if (it + 1 < 16) { pref(it + 1, buf ^ 1); cp_commit(); }
#pragma unroll
        for (int k = 0; k < 16; k++) {
            float4 av = *(const float4*)&As[buf][k][ty * 4];
            u64 aa[4];
            aa[0] = pack2(av.x, av.x); aa[1] = pack2(av.y, av.y);
            aa[2] = pack2(av.z, av.z); aa[3] = pack2(av.w, av.w);
#pragma unroll
            for (int p = 0; p < 4; p++) {
                float2 bp = *(const float2*)&Bs[buf][k][2 * (tx + 16 * p)];
                u64 bb = pack2(bp.x, bp.y);
#pragma unroll
                for (int i = 0; i < 4; i++) acc[i][p] = fma2(aa[i], bb, acc[i][p]);
            }
        }
        __syncthreads();
    }

    if (j0 < DI) {
#pragma unroll
        for (int i = 0; i < 4; i++) {
            int l = l0 + ty * 4 + i;
#pragma unroll
            for (int p = 0; p < 4; p++) {
                float lo, hi; unpack2(acc[i][p], lo, hi);
                int j = j0 + 2 * (tx + 16 * p);
                float2 v; v.x = lo; v.y = hi;
                *(float2*)&g_xs[(b * LSEQ + l) * DI + j] = v;
            }
        }
    } else {
        // z half: silu + transposed store [d][l]
        float lv[4][4], hv[4][4];
#pragma unroll
        for (int i = 0; i < 4; i++)
#pragma unroll
            for (int p = 0; p < 4; p++) unpack2(acc[i][p], lv[i][p], hv[i][p]);
#pragma unroll
        for (int p = 0; p < 4; p++) {
            int jbase = (j0 - DI) + 2 * (tx + 16 * p);
            float4 v0, v1;
            v0.x = silu_f(lv[0][p]); v0.y = silu_f(lv[1][p]);
            v0.z = silu_f(lv[2][p]); v0.w = silu_f(lv[3][p]);
            v1.x = silu_f(hv[0][p]); v1.y = silu_f(hv[1][p]);
            v1.z = silu_f(hv[2][p]); v1.w = silu_f(hv[3][p]);
            *(float4*)&g_szT[(b * DI + jbase)     * LSEQ + l0 + ty * 4] = v0;
            *(float4*)&g_szT[(b * DI + jbase + 1) * LSEQ + l0 + ty * 4] = v1;
        }
    }
}

// ============================================================================
// K2: causal depthwise conv(4) + silu -> xc [d][l]; dbc = xc @ W_x;
//     dt = softplus(dbc[:, :16] @ W_dt + b_dt) -> [d][l];
//     B/C packed [l/4][s][l%4].   (R11 exact)
// ============================================================================
__global__ __launch_bounds__(256) void k_conv_proj(const float* __restrict__ convw,
                                                   const float* __restrict__ convb,
                                                   const float* __restrict__ Wx,
                                                   const float* __restrict__ Wdt,
                                                   const float* __restrict__ bdt) {
    __shared__ float xc_s[32][257];   // reused as dt staging in phase C
    __shared__ float dbc_s[32][49];
    const int t  = threadIdx.x;
    const int b  = blockIdx.x >> 7;
    const int l0 = (blockIdx.x & 127) * 32;

    // ---- Phase A: conv + silu (thread t owns channel d = t) ----
    {
        const int d = t;
        const float w0 = convw[d * 4 + 0], w1 = convw[d * 4 + 1];
        const float w2 = convw[d * 4 + 2], w3 = convw[d * 4 + 3];
        const float cb = convb[d];
        const float* pxs = g_xs + b * LSEQ * DI + d;
        float x0, x1, x2;
        if (l0 == 0) { x0 = x1 = x2 = 0.f; }
        else { x0 = pxs[(l0 - 3) * DI]; x1 = pxs[(l0 - 2) * DI]; x2 = pxs[(l0 - 1) * DI]; }
        for (int j = 0; j < 32; j++) {
            float x3 = pxs[(l0 + j) * DI];
            float c  = cb + w0 * x0 + w1 * x1 + w2 * x2 + w3 * x3;
            xc_s[j][d] = silu_f(c);
            x0 = x1; x1 = x2; x2 = x3;
        }
    }
    __syncthreads();

    // ---- transposed coalesced write of xc to [d][l] ----
    for (int i = t; i < 32 * DI; i += 256) {
        int d2 = i >> 5, r2 = i & 31;
        g_xc[(b * DI + d2) * LSEQ + l0 + r2] = xc_s[r2][d2];
    }

    // ---- Phase B: dbc[r][0..47] = xc[r] @ W_x ----
    {
        const int r = t & 31, g = t >> 5;   // g in 0..7, 6 cols each
        float acc[6];
#pragma unroll
        for (int jj = 0; jj < 6; jj++) acc[jj] = 0.f;
        const float* wbase = Wx + g * 6;
        for (int c = 0; c < DI; c++) {
            float xv = xc_s[r][c];
            const float2* wp = (const float2*)(wbase + c * 48);
            float2 wa = __ldg(wp), wb = __ldg(wp + 1), wc = __ldg(wp + 2);
            acc[0] = fmaf(xv, wa.x, acc[0]); acc[1] = fmaf(xv, wa.y, acc[1]);
            acc[2] = fmaf(xv, wb.x, acc[2]); acc[3] = fmaf(xv, wb.y, acc[3]);
            acc[4] = fmaf(xv, wc.x, acc[4]); acc[5] = fmaf(xv, wc.y, acc[5]);
        }
#pragma unroll
        for (int jj = 0; jj < 6; jj++) dbc_s[r][g * 6 + jj] = acc[jj];
    }
    __syncthreads();

    // ---- Phase C: dt = softplus(dbc[:, :16] @ W_dt + b_dt) into xc_s ----
    {
        const int d = t;
        float wdt[16];
#pragma unroll
        for (int k = 0; k < 16; k++) wdt[k] = Wdt[k * DI + d];
        const float bd = bdt[d];
        for (int r = 0; r < 32; r++) {
            float a = bd;
#pragma unroll
            for (int k = 0; k < 16; k++) a = fmaf(dbc_s[r][k], wdt[k], a);
            xc_s[r][d] = (a > 20.f) ? a : log1pf(__expf(a));
        }
    }
    __syncthreads();

    // ---- transposed coalesced write of dt to [d][l] ----
    for (int i = t; i < 32 * DI; i += 256) {
        int d2 = i >> 5, r2 = i & 31;
        g_dt[(b * DI + d2) * LSEQ + l0 + r2] = xc_s[r2][d2];
    }

    // ---- packed coalesced write of B / C: [l/4][s][l%4] ----
    {
        const int base = (b * LSEQ + l0) * DS;
        for (int i = t; i < 32 * DS; i += 256) {
            int g4 = i >> 6, s = (i >> 2) & 15, r2 = i & 3;
            int r = g4 * 4 + r2;
            g_Bm[base + i] = dbc_s[r][16 + s];
            g_Cm[base + i] = dbc_s[r][32 + s];
        }
    }
}

// ============================================================================
// K3a: per-chunk local scan -> S (final h with h0=0) and P = exp2(A2 * sum dt).
// Block = 16 d's x one chunk; working set staged in smem via one cp.async burst.
// (R11 exact)
// ============================================================================
__global__ __launch_bounds__(256) void k_scan1(const float* __restrict__ Alog) {
    __shared__ __align__(16) float s_dt[16 * ROWP];
    __shared__ __align__(16) float s_xc[16 * ROWP];
    __shared__ __align__(16) float s_B [CHUNK * DS];

    const int t  = threadIdx.x;
    const int dg    = blockIdx.x & 15;
    const int chunk = (blockIdx.x >> 4) & (NC - 1);
    const int b     = blockIdx.x >> 9;
    const int d0 = dg * 16;
    const int l0 = chunk * CHUNK;

    const float* pdt_g = g_dt + (b * DI + d0) * LSEQ + l0;
    const float* pxc_g = g_xc + (b * DI + d0) * LSEQ + l0;
    const float* pB_g  = g_Bm + (b * LSEQ + l0) * DS;

#pragma unroll
    for (int i = t; i < 512 * 3; i += 256) {
        int r = i >> 9, j = i & 511;
        int w = j >> 5, j16 = (j & 31) * 4;
        if (r == 0)      cp_async16(&s_dt[w * ROWP + j16], pdt_g + w * LSEQ + j16);
        else if (r == 1) cp_async16(&s_xc[w * ROWP + j16], pxc_g + w * LSEQ + j16);
        else             cp_async16(&s_B[j * 4], pB_g + j * 4);
    }
    cp_commit(); cp_wait0();
    __syncthreads();

    const int w = t >> 4, s = t & 15;
    const int d = d0 + w;
    const float A2 = -__expf(Alog[d * DS + s]) * LOG2E;
    const float* sdt = s_dt + w * ROWP;
    const float* sxc = s_xc + w * ROWP;
    const float* sB  = s_B + s * 4;

    float h = 0.f, dts = 0.f;
#pragma unroll 8
    for (int l = 0; l < CHUNK; l += 4) {
        float4 dv = *(const float4*)(sdt + l);
        float4 xv = *(const float4*)(sxc + l);
        float4 Bv = *(const float4*)(sB + (l >> 2) * 64);
        h = fmaf(h, ex2f(dv.x * A2), dv.x * xv.x * Bv.x);
        h = fmaf(h, ex2f(dv.y * A2), dv.y * xv.y * Bv.y);
        h = fmaf(h, ex2f(dv.z * A2), dv.z * xv.z * Bv.z);
        h = fmaf(h, ex2f(dv.w * A2), dv.w * xv.w * Bv.w);
        dts += (dv.x + dv.y) + (dv.z + dv.w);
    }
    const int idx = ((b * DI + d) * NC + chunk) * DS + s;
    g_S[idx] = h;
    g_P[idx] = ex2f(A2 * dts);
}

// ============================================================================
// K3b: per-chunk scan with true initial state (self-stitched prefix).
// CHANGE vs R11: sz is NOT staged in smem — read via coalesced LDG at store
// time (off the h-chain critical path). Fill 40KB -> 32KB; smem/block
// 41.6KB -> 33.2KB -> 6 blocks/SM (occupancy 51% -> ~72%).
// ============================================================================
__global__ __launch_bounds__(256) void k_scan3(const float* __restrict__ Alog,
                                               const float* __restrict__ Dvec) {
    __shared__ __align__(16) float s_dt[16 * ROWP];
    __shared__ __align__(16) float s_xc[16 * ROWP];
    __shared__ __align__(16) float s_B [CHUNK * DS];
    __shared__ __align__(16) float s_C [CHUNK * DS];

    const int t  = threadIdx.x;
    const int dg    = blockIdx.x & 15;
    const int chunk = (blockIdx.x >> 4) & (NC - 1);
    const int b     = blockIdx.x >> 9;
    const int d0 = dg * 16;
    const int l0 = chunk * CHUNK;

    const float* pdt_g = g_dt  + (b * DI + d0) * LSEQ + l0;
    const float* pxc_g = g_xc  + (b * DI + d0) * LSEQ + l0;
    const float* pB_g  = g_Bm  + (b * LSEQ + l0) * DS;
    const float* pC_g  = g_Cm  + (b * LSEQ + l0) * DS;

#pragma unroll
    for (int i = t; i < 512 * 4; i += 256) {
        int r = i >> 9, j = i & 511;
        int w = j >> 5, j16 = (j & 31) * 4;
        if (r == 0)      cp_async16(&s_dt[w * ROWP + j16], pdt_g + w * LSEQ + j16);
        else if (r == 1) cp_async16(&s_xc[w * ROWP + j16], pxc_g + w * LSEQ + j16);
        else if (r == 2) cp_async16(&s_B[j * 4], pB_g + j * 4);
        else             cp_async16(&s_C[j * 4], pC_g + j * 4);
    }
    cp_commit();

    const int w = t >> 4, s = t & 15;
    const int d = d0 + w;
    const float A2 = -__expf(Alog[d * DS + s]) * LOG2E;
    const float Dd = Dvec[d];
    const float* psz = g_szT + (b * DI + d) * LSEQ + l0;   // direct gmem reads
    float*       pyT = g_ymT + (b * DI + d) * LSEQ + l0;

    // ---- self-stitched prefix (overlaps with the cp.async fill) ----
    float h = 0.f;
    {
        const int pbase = (b * DI + d) * NC * DS + s;
#pragma unroll
        for (int c = 0; c < NC - 1; c++) {
            if (c < chunk) h = fmaf(g_P[pbase + c * DS], h, g_S[pbase + c * DS]);
        }
    }

    cp_wait0();
    __syncthreads();

    const float* sdt = s_dt + w * ROWP;
    const float* sxc = s_xc + w * ROWP;
    const float* sB  = s_B + s * 4;
    const float* sC  = s_C + s * 4;

    for (int l = 0; l < CHUNK; l += 16) {
        float zs = psz[l + s];              // coalesced 64B LDG per half-warp
        float wv[16];
#pragma unroll
        for (int g = 0; g < 4; g++) {
            float4 dv = *(const float4*)(sdt + l + g * 4);
            float4 xv = *(const float4*)(sxc + l + g * 4);
            float4 Bv = *(const float4*)(sB + ((l >> 2) + g) * 64);
            float4 Cv = *(const float4*)(sC + ((l >> 2) + g) * 64);
            h = fmaf(h, ex2f(dv.x * A2), dv.x * xv.x * Bv.x); wv[g * 4 + 0] = h * Cv.x;
            h = fmaf(h, ex2f(dv.y * A2), dv.y * xv.y * Bv.y); wv[g * 4 + 1] = h * Cv.y;
            h = fmaf(h, ex2f(dv.z * A2), dv.z * xv.z * Bv.z); wv[g * 4 + 2] = h * Cv.z;
            h = fmaf(h, ex2f(dv.w * A2), dv.w * xv.w * Bv.w); wv[g * 4 + 3] = h * Cv.w;
        }
        float y  = hreduce16(wv, s);
        float xs = sxc[l + s];
        pyT[l + s] = fmaf(xs, Dd, y) * zs;
    }
}

// ============================================================================
// K4: out-projection GEMM.  out[b,c,l] = sum_d ymT[b,d,l] * W_out[d,c]
// 64(c) x 128(l) tiles, K-tiles of 16 over d, cp.async double-buffered.
// (R11 exact)
// ============================================================================
__global__ __launch_bounds__(256) void k_outproj(const float* __restrict__ Wout,
                                                 float* __restrict__ out) {
    __shared__ float As[2][16][64];
    __shared__ float Bs[2][16][132];
    const int t  = threadIdx.x;
    const int l0 = blockIdx.x * 128, c0 = blockIdx.y * 64, b = blockIdx.z;
    const int ty = t >> 4, tx = t & 15;

    u64 acc[4][4];
#pragma unroll
    for (int i = 0; i < 4; i++)
#pragma unroll
        for (int p = 0; p < 4; p++) acc[i][p] = 0ull;

    const float* ymb = g_ymT + b * DI * LSEQ;
    const int ka = t >> 4, ca = (t & 15) * 4;
    auto pref = [&](int tile, int buf) {
        cp_async16(&As[buf][ka][ca], Wout + (tile * 16 + ka) * DM + c0 + ca);
#pragma unroll
        for (int i = 0; i < 2; i++) {
            int idx = t + i * 256;
            int kb = idx >> 5, lb = (idx & 31) * 4;
            cp_async16(&Bs[buf][kb][lb], ymb + (tile * 16 + kb) * LSEQ + l0 + lb);
        }
    };

    pref(0, 0); cp_commit();

    for (int it = 0; it < 16; it++) {
        const int buf = it & 1;
        cp_wait0();
        __syncthreads();
        if (it + 1 < 16) { pref(it + 1, buf ^ 1); cp_commit(); }
#pragma unroll
        for (int k = 0; k < 16; k++) {
            float4 av = *(const float4*)&As[buf][k][ty * 4];
            u64 aa[4];
            aa[0] = pack2(av.x, av.x); aa[1] = pack2(av.y, av.y);
            aa[2] = pack2(av.z, av.z); aa[3] = pack2(av.w, av.w);
#pragma unroll
            for (int p = 0; p < 4; p++) {
                float2 bp = *(const float2*)&Bs[buf][k][2 * (tx + 16 * p)];
                u64 bb = pack2(bp.x, bp.y);
#pragma unroll
                for (int i = 0; i < 4; i++) acc[i][p] = fma2(aa[i], bb, acc[i][p]);
            }
        }
        __syncthreads();
    }

#pragma unroll
    for (int i = 0; i < 4; i++) {
        int c = c0 + ty * 4 + i;
#pragma unroll
        for (int p = 0; p < 4; p++) {
            float lo, hi; unpack2(acc[i][p], lo, hi);
            int lc = l0 + 2 * (tx + 16 * p);
            float2 v; v.x = lo; v.y = hi;
            *(float2*)&out[(b * DM + c) * LSEQ + lc] = v;
        }
    }
}

// ============================================================================
extern "C" void kernel_launch(void* const* d_in, const int* in_sizes, int n_in,
                              void* d_out, int out_size) {
    (void)in_sizes; (void)n_in; (void)out_size;
    const float* x     = (const float*)d_in[0];
    const float* Win   = (const float*)d_in[1];
    const float* convw = (const float*)d_in[2];
    const float* convb = (const float*)d_in[3];
    const float* Wx    = (const float*)d_in[4];
    const float* Wdt   = (const float*)d_in[5];
    const float* bdt   = (const float*)d_in[6];
    const float* Alog  = (const float*)d_in[7];
    const float* Dvec  = (const float*)d_in[8];
    const float* Wout  = (const float*)d_in[9];
    float* out = (float*)d_out;

    k_inproj   <<<dim3(64, 4, 2), 256>>>(x, Win);
    k_conv_proj<<<256, 256>>>(convw, convb, Wx, Wdt, bdt);
    k_scan1    <<<1024, 256>>>(Alog);
    k_scan3    <<<1024, 256>>>(Alog, Dvec);
    k_outproj  <<<dim3(32, 4, 2), 256>>>(Wout, out);
}